// round 1
// baseline (speedup 1.0000x reference)
#include <cuda_runtime.h>

#define BB 128
#define LL 512
#define KN 8
#define DD 300
#define CC 14
#define LCHUNK 16
#define NCHUNK (LL / LCHUNK)   // 32

// Deterministic partial-sum scratch: [chunk][b][d]
__device__ float g_part[NCHUNK * BB * DD];

__global__ __launch_bounds__(256)
void gnn_pool_kernel(const int* __restrict__ master,
                     const int* __restrict__ slave,
                     const int* __restrict__ edge,
                     const float* __restrict__ R,
                     const float* __restrict__ E,
                     const float* __restrict__ Ngate)
{
    const int b     = blockIdx.y;
    const int chunk = blockIdx.x;
    const int tid   = threadIdx.x;

    __shared__ int   s_node[KN];
    __shared__ float s_e[KN];
    __shared__ int   s_m;
    __shared__ float s_g;

    float acc0 = 0.f, acc1 = 0.f;
    const int base = b * LL + chunk * LCHUNK;

    for (int li = 0; li < LCHUNK; ++li) {
        const int pos = base + li;
        if (tid < KN) {
            const int sn = slave[pos * KN + tid];
            s_node[tid] = sn;
            s_e[tid]    = E[edge[pos * KN + tid]];
        } else if (tid == 32) {
            const int m = master[pos];
            s_m = m;
            s_g = Ngate[m];
        }
        __syncthreads();

        const int   m = s_m;
        const float g = s_g;

        // slice 0: d = tid (0..255)
        {
            const int d = tid;
            float mx = R[s_node[0] * DD + d] * s_e[0];
            #pragma unroll
            for (int k = 1; k < KN; ++k)
                mx = fmaxf(mx, R[s_node[k] * DD + d] * s_e[k]);
            const float rm = R[m * DD + d];
            acc0 += (1.f - g) * mx + g * rm;
        }
        // slice 1: d = tid + 256 (only tid < 44)
        if (tid < DD - 256) {
            const int d = tid + 256;
            float mx = R[s_node[0] * DD + d] * s_e[0];
            #pragma unroll
            for (int k = 1; k < KN; ++k)
                mx = fmaxf(mx, R[s_node[k] * DD + d] * s_e[k]);
            const float rm = R[m * DD + d];
            acc1 += (1.f - g) * mx + g * rm;
        }
        __syncthreads();
    }

    float* outp = &g_part[(chunk * BB + b) * DD];
    outp[tid] = acc0;
    if (tid < DD - 256) outp[tid + 256] = acc1;
}

__global__ __launch_bounds__(256)
void head_kernel(const float* __restrict__ W,
                 const float* __restrict__ bias,
                 float* __restrict__ out)
{
    const int b   = blockIdx.x;
    const int tid = threadIdx.x;

    __shared__ float sx[DD];
    __shared__ float sh[CC];

    // Reduce the 32 partials -> X[b][:]
    for (int d = tid; d < DD; d += 256) {
        float s = 0.f;
        #pragma unroll
        for (int c = 0; c < NCHUNK; ++c)
            s += g_part[(c * BB + b) * DD + d];
        sx[d] = s;
    }
    __syncthreads();

    // h[c] = relu(X . W[c] + bias[c]) : 14 classes x 16 threads each
    if (tid < CC * 16) {
        const int c = tid >> 4;
        const int i = tid & 15;
        float s = 0.f;
        for (int d = i; d < DD; d += 16)
            s += sx[d] * W[c * DD + d];
        #pragma unroll
        for (int off = 8; off; off >>= 1)
            s += __shfl_down_sync(0xffffffffu, s, off, 16);
        if (i == 0)
            sh[c] = fmaxf(s + bias[c], 0.f);
    }
    __syncthreads();

    // Softmax over 14 classes (serial — trivial)
    if (tid == 0) {
        float m = sh[0];
        #pragma unroll
        for (int c = 1; c < CC; ++c) m = fmaxf(m, sh[c]);
        float e[CC];
        float sum = 0.f;
        #pragma unroll
        for (int c = 0; c < CC; ++c) { e[c] = expf(sh[c] - m); sum += e[c]; }
        const float inv = 1.f / sum;
        #pragma unroll
        for (int c = 0; c < CC; ++c) out[b * CC + c] = e[c] * inv;
    }
}

extern "C" void kernel_launch(void* const* d_in, const int* in_sizes, int n_in,
                              void* d_out, int out_size)
{
    const int*   master = (const int*)  d_in[0];
    const int*   slave  = (const int*)  d_in[1];
    const int*   edge   = (const int*)  d_in[2];
    const float* R      = (const float*)d_in[3];
    const float* E      = (const float*)d_in[4];
    const float* Ngate  = (const float*)d_in[5];
    const float* W      = (const float*)d_in[6];
    const float* bias   = (const float*)d_in[7];
    float* out = (float*)d_out;

    gnn_pool_kernel<<<dim3(NCHUNK, BB), 256>>>(master, slave, edge, R, E, Ngate);
    head_kernel<<<BB, 256>>>(W, bias, out);
}

// round 2
// speedup vs baseline: 1.2914x; 1.2914x over previous
#include <cuda_runtime.h>

#define BB 128
#define LL 512
#define KN 8
#define DD 300
#define CC 14
#define LCHUNK 64
#define NCHUNK (LL / LCHUNK)   // 8

// Deterministic partial-sum scratch: [chunk][b][d]
__device__ float g_part[NCHUNK * BB * DD];

__global__ __launch_bounds__(256)
void gnn_pool_kernel(const int* __restrict__ master,
                     const int* __restrict__ slave,
                     const int* __restrict__ edge,
                     const float* __restrict__ R,
                     const float* __restrict__ E,
                     const float* __restrict__ Ngate)
{
    const int b     = blockIdx.y;
    const int chunk = blockIdx.x;
    const int tid   = threadIdx.x;

    __shared__ int   s_node[LCHUNK * KN];
    __shared__ float s_e[LCHUNK * KN];
    __shared__ int   s_m[LCHUNK];
    __shared__ float s_g[LCHUNK];

    const int base = b * LL + chunk * LCHUNK;

    // ---- Cooperative metadata load: 512 slaves/edges + 64 masters/gates ----
    {
        // 512 entries, 256 threads -> 2 each
        #pragma unroll
        for (int r = 0; r < 2; ++r) {
            const int i = tid + r * 256;           // 0..511
            const int pos = base + (i >> 3);       // position within chunk
            const int k   = i & 7;
            s_node[i] = slave[pos * KN + k];
            s_e[i]    = E[edge[pos * KN + k]];
        }
        if (tid < LCHUNK) {
            const int m = master[base + tid];
            s_m[tid] = m;
            s_g[tid] = Ngate[m];
        }
    }
    __syncthreads();

    float acc0 = 0.f, acc1 = 0.f;
    const bool tail = (tid < DD - 256);   // threads 0..43 also handle d+256

    #pragma unroll 2
    for (int li = 0; li < LCHUNK; ++li) {
        const int*   np = &s_node[li * KN];
        const float* ep = &s_e[li * KN];
        const int    m  = s_m[li];
        const float  g  = s_g[li];

        // slice 0: d = tid
        {
            const int d = tid;
            float mx = __ldg(&R[np[0] * DD + d]) * ep[0];
            #pragma unroll
            for (int k = 1; k < KN; ++k)
                mx = fmaxf(mx, __ldg(&R[np[k] * DD + d]) * ep[k]);
            const float rm = __ldg(&R[m * DD + d]);
            acc0 += mx + g * (rm - mx);
        }
        // slice 1: d = tid + 256
        if (tail) {
            const int d = tid + 256;
            float mx = __ldg(&R[np[0] * DD + d]) * ep[0];
            #pragma unroll
            for (int k = 1; k < KN; ++k)
                mx = fmaxf(mx, __ldg(&R[np[k] * DD + d]) * ep[k]);
            const float rm = __ldg(&R[m * DD + d]);
            acc1 += mx + g * (rm - mx);
        }
    }

    float* outp = &g_part[(chunk * BB + b) * DD];
    outp[tid] = acc0;
    if (tail) outp[tid + 256] = acc1;
}

__global__ __launch_bounds__(256)
void head_kernel(const float* __restrict__ W,
                 const float* __restrict__ bias,
                 float* __restrict__ out)
{
    const int b   = blockIdx.x;
    const int tid = threadIdx.x;

    __shared__ float sx[DD];
    __shared__ float sh[CC];

    // Reduce the 8 partials -> X[b][:]
    for (int d = tid; d < DD; d += 256) {
        float s = 0.f;
        #pragma unroll
        for (int c = 0; c < NCHUNK; ++c)
            s += g_part[(c * BB + b) * DD + d];
        sx[d] = s;
    }
    __syncthreads();

    // h[c] = relu(X . W[c] + bias[c]) : 14 classes x 16 threads each
    if (tid < CC * 16) {
        const int c = tid >> 4;
        const int i = tid & 15;
        float s = 0.f;
        for (int d = i; d < DD; d += 16)
            s += sx[d] * W[c * DD + d];
        #pragma unroll
        for (int off = 8; off; off >>= 1)
            s += __shfl_down_sync(0xffffffffu, s, off, 16);
        if (i == 0)
            sh[c] = fmaxf(s + bias[c], 0.f);
    }
    __syncthreads();

    // Softmax over 14 classes
    if (tid == 0) {
        float m = sh[0];
        #pragma unroll
        for (int c = 1; c < CC; ++c) m = fmaxf(m, sh[c]);
        float e[CC];
        float sum = 0.f;
        #pragma unroll
        for (int c = 0; c < CC; ++c) { e[c] = expf(sh[c] - m); sum += e[c]; }
        const float inv = 1.f / sum;
        #pragma unroll
        for (int c = 0; c < CC; ++c) out[b * CC + c] = e[c] * inv;
    }
}

extern "C" void kernel_launch(void* const* d_in, const int* in_sizes, int n_in,
                              void* d_out, int out_size)
{
    const int*   master = (const int*)  d_in[0];
    const int*   slave  = (const int*)  d_in[1];
    const int*   edge   = (const int*)  d_in[2];
    const float* R      = (const float*)d_in[3];
    const float* E      = (const float*)d_in[4];
    const float* Ngate  = (const float*)d_in[5];
    const float* W      = (const float*)d_in[6];
    const float* bias   = (const float*)d_in[7];
    float* out = (float*)d_out;

    gnn_pool_kernel<<<dim3(NCHUNK, BB), 256>>>(master, slave, edge, R, E, Ngate);
    head_kernel<<<BB, 256>>>(W, bias, out);
}

// round 3
// speedup vs baseline: 2.0286x; 1.5708x over previous
#include <cuda_runtime.h>
#include <cuda_fp16.h>

#define BB 128
#define LL 512
#define KN 8
#define DD 300
#define CC 14
#define LCHUNK 64
#define NCHUNK (LL / LCHUNK)   // 8
#define NROWS 4905             // NUM_NODES + 1
#define RSTRIDE 320            // halves per row: 640B = 5 x 128B sectors

// fp16 copy of R, row-padded for sector alignment
__device__ __half g_Rh[NROWS * RSTRIDE];
// Deterministic partial-sum scratch: [chunk][b][d]
__device__ float g_part[NCHUNK * BB * DD];

__global__ __launch_bounds__(320)
void convert_kernel(const float* __restrict__ R)
{
    const int row = blockIdx.x;
    const int c   = threadIdx.x;
    if (c < DD)
        g_Rh[row * RSTRIDE + c] = __float2half(R[row * DD + c]);
}

__global__ __launch_bounds__(160)
void gnn_pool_kernel(const int* __restrict__ master,
                     const int* __restrict__ slave,
                     const int* __restrict__ edge,
                     const float* __restrict__ E,
                     const float* __restrict__ Ngate)
{
    const int b     = blockIdx.y;
    const int chunk = blockIdx.x;
    const int tid   = threadIdx.x;

    __shared__ int   s_node[LCHUNK * KN];
    __shared__ float s_e[LCHUNK * KN];
    __shared__ int   s_m[LCHUNK];
    __shared__ float s_g[LCHUNK];

    const int base = b * LL + chunk * LCHUNK;

    // Cooperative metadata load: 512 slaves/edges + 64 masters/gates
    for (int i = tid; i < LCHUNK * KN; i += 160) {
        const int pos = base + (i >> 3);
        const int k   = i & 7;
        s_node[i] = slave[pos * KN + k];
        s_e[i]    = E[edge[pos * KN + k]];
    }
    if (tid < LCHUNK) {
        const int m = master[base + tid];
        s_m[tid] = m;
        s_g[tid] = Ngate[m];
    }
    __syncthreads();

    if (tid >= 150) return;   // 150 half2 lanes cover 300 dims

    float2 acc = make_float2(0.f, 0.f);

    #pragma unroll 2
    for (int li = 0; li < LCHUNK; ++li) {
        const int*   np = &s_node[li * KN];
        const float* ep = &s_e[li * KN];
        const int    m  = s_m[li];
        const float  g  = s_g[li];

        const __half2* r0 = (const __half2*)(g_Rh + (size_t)np[0] * RSTRIDE);
        float2 f = __half22float2(r0[tid]);
        float mx0 = f.x * ep[0];
        float mx1 = f.y * ep[0];
        #pragma unroll
        for (int k = 1; k < KN; ++k) {
            const __half2* rk = (const __half2*)(g_Rh + (size_t)np[k] * RSTRIDE);
            float2 fk = __half22float2(rk[tid]);
            mx0 = fmaxf(mx0, fk.x * ep[k]);
            mx1 = fmaxf(mx1, fk.y * ep[k]);
        }
        const __half2* rm = (const __half2*)(g_Rh + (size_t)m * RSTRIDE);
        float2 fm = __half22float2(rm[tid]);

        acc.x += mx0 + g * (fm.x - mx0);
        acc.y += mx1 + g * (fm.y - mx1);
    }

    float2* outp = (float2*)&g_part[(chunk * BB + b) * DD];
    outp[tid] = acc;
}

__global__ __launch_bounds__(448)
void head_kernel(const float* __restrict__ W,
                 const float* __restrict__ bias,
                 float* __restrict__ out)
{
    const int b    = blockIdx.x;
    const int tid  = threadIdx.x;
    const int wid  = tid >> 5;
    const int lane = tid & 31;

    __shared__ float sx[DD];
    __shared__ float sh[CC];

    // Reduce the 8 partials -> X[b][:]  (one pass, 448 threads cover 300)
    if (tid < DD) {
        float s = 0.f;
        #pragma unroll
        for (int c = 0; c < NCHUNK; ++c)
            s += g_part[(c * BB + b) * DD + tid];
        sx[tid] = s;
    }
    __syncthreads();

    // One warp per class: h[c] = relu(X . W[c] + bias[c])
    if (wid < CC) {
        float s = 0.f;
        for (int d = lane; d < DD; d += 32)
            s += sx[d] * W[wid * DD + d];
        #pragma unroll
        for (int off = 16; off; off >>= 1)
            s += __shfl_down_sync(0xffffffffu, s, off);
        if (lane == 0)
            sh[wid] = fmaxf(s + bias[wid], 0.f);
    }
    __syncthreads();

    // Softmax over 14 classes
    if (tid == 0) {
        float m = sh[0];
        #pragma unroll
        for (int c = 1; c < CC; ++c) m = fmaxf(m, sh[c]);
        float e[CC];
        float sum = 0.f;
        #pragma unroll
        for (int c = 0; c < CC; ++c) { e[c] = expf(sh[c] - m); sum += e[c]; }
        const float inv = 1.f / sum;
        #pragma unroll
        for (int c = 0; c < CC; ++c) out[b * CC + c] = e[c] * inv;
    }
}

extern "C" void kernel_launch(void* const* d_in, const int* in_sizes, int n_in,
                              void* d_out, int out_size)
{
    const int*   master = (const int*)  d_in[0];
    const int*   slave  = (const int*)  d_in[1];
    const int*   edge   = (const int*)  d_in[2];
    const float* R      = (const float*)d_in[3];
    const float* E      = (const float*)d_in[4];
    const float* Ngate  = (const float*)d_in[5];
    const float* W      = (const float*)d_in[6];
    const float* bias   = (const float*)d_in[7];
    float* out = (float*)d_out;

    convert_kernel<<<NROWS, 320>>>(R);
    gnn_pool_kernel<<<dim3(NCHUNK, BB), 160>>>(master, slave, edge, E, Ngate);
    head_kernel<<<BB, 448>>>(W, bias, out);
}